// round 16
// baseline (speedup 1.0000x reference)
#include <cuda_runtime.h>
#include <cuda_fp16.h>
#include <cstdint>

#define BB 32
#define SS 2048
#define HH 1024
#define D2H 2048

// Scratch (device globals — no allocation allowed)
__device__ float g_wq[BB * HH];            // W(dh) + W_b + U_b
__device__ float g_spart[8 * BB * SS];     // per-N-chunk partial scores
__device__ float g_weights[BB * SS];
__device__ float g_part[8 * BB * D2H];
__device__ __half g_enc16[(size_t)BB * SS * D2H];   // fp16 mirror of enc (268MB)

__device__ __forceinline__ uint32_t f2h2(float x, float y) {
    __half2 h = __floats2half2_rn(x, y);
    return *reinterpret_cast<uint32_t*>(&h);
}
__device__ __forceinline__ uint32_t s2u(const void* p) {
    uint32_t a;
    asm("{ .reg .u64 t; cvta.to.shared.u64 t, %1; cvt.u32.u64 %0, t; }"
        : "=r"(a) : "l"(p));
    return a;
}
__device__ __forceinline__ void ldsm_x4(uint32_t& r0, uint32_t& r1,
                                        uint32_t& r2, uint32_t& r3,
                                        uint32_t addr) {
    asm volatile("ldmatrix.sync.aligned.m8n8.x4.shared.b16 {%0,%1,%2,%3}, [%4];"
                 : "=r"(r0), "=r"(r1), "=r"(r2), "=r"(r3) : "r"(addr));
}

// ---------------------------------------------------------------------------
// Kernel A: wq[b][k] = dh[b]·W_w[k] + W_b[k] + U_b[k]
// ---------------------------------------------------------------------------
__global__ void wq_kernel(const float* __restrict__ dh,
                          const float* __restrict__ W_w,
                          const float* __restrict__ W_b,
                          const float* __restrict__ U_b) {
    int b = blockIdx.x;
    int k = blockIdx.y * 128 + threadIdx.x;
    __shared__ float dh_s[HH];
    for (int i = threadIdx.x; i < HH; i += 128) dh_s[i] = dh[b * HH + i];
    __syncthreads();
    const float4* wrow = reinterpret_cast<const float4*>(W_w + (size_t)k * HH);
    const float4* dv   = reinterpret_cast<const float4*>(dh_s);
    float acc = 0.f;
#pragma unroll 8
    for (int i = 0; i < HH / 4; i++) {
        float4 w = wrow[i];
        float4 d = dv[i];
        acc += w.x * d.x + w.y * d.y + w.z * d.z + w.w * d.w;
    }
    g_wq[b * HH + k] = acc + W_b[k] + U_b[k];
}

// ---------------------------------------------------------------------------
// Kernel B: fused GEMM(enc @ U^T) + tanh + V-dot -> partial scores
// Grid 4096: nc = bx&7 fastest (8 N-chunk CTAs share the A tile via L2).
// CTA 128x128, fp16 mma.sync.m16n8k16 fp32-accum, ldmatrix fragment loads.
// nc==0 CTAs side-write the converted fp16 A tile to g_enc16 for ctx_part.
// 8 warps as 4(M) x 2(N); K-chunk = 64 elements; 2 CTAs/SM.
// ---------------------------------------------------------------------------
#define LDW 36   // smem row stride in 32-bit words (32 half2 + 4 pad)

__global__ __launch_bounds__(256, 2)
void score_kernel(const float* __restrict__ enc,
                  const float* __restrict__ Uw,
                  const float* __restrict__ Vw) {
    __shared__ uint32_t A_s[128 * LDW];   // enc tile  [m][k] as half2 words
    __shared__ uint32_t B_s[128 * LDW];   // U_w tile  [n][k] as half2 words
    __shared__ float wq_s[128];
    __shared__ float V_s[128];
    __shared__ float scores_s[128];

    const int tid  = threadIdx.x;
    const int lane = tid & 31;
    const int warp = tid >> 5;
    const int wm   = warp & 3;    // warp row (0..3) -> 32 rows each
    const int wn   = warp >> 2;   // warp col (0..1) -> 64 cols each
    const int gid  = lane >> 2;   // group id (0..7)
    const int tig  = lane & 3;    // thread-in-group

    const int nc    = blockIdx.x & 7;
    const int mtile = blockIdx.x >> 3;
    const int b     = mtile >> 4;
    const int stile = mtile & 15;

    // Loader coords: seg = 4-float segment (0..15), rows row0 + 16*i
    const int seg  = tid & 15;
    const int row0 = tid >> 4;    // 0..15
    const float* Abase =
        enc + ((size_t)(b * SS + stile * 128) + row0) * D2H + seg * 4;
    const float* Bbase =
        Uw + ((size_t)(nc * 128) + row0) * D2H + seg * 4;
    __half* e16base =
        g_enc16 + ((size_t)(b * SS + stile * 128) + row0) * D2H + seg * 4;

    if (tid < 128) {
        scores_s[tid] = 0.f;
        wq_s[tid] = g_wq[b * HH + nc * 128 + tid];
        V_s[tid]  = Vw[nc * 128 + tid];
    }

    // ldmatrix per-lane base addresses (byte, shared space).
    const int   rowA  = wm * 32 + (lane & 7) + ((lane >> 3) & 1) * 8;
    const int   wA    = ((lane >> 4) & 1) * 4;
    const uint32_t aAddr0 = s2u(A_s) + (uint32_t)(rowA * LDW + wA) * 4u;
    const int   rowB  = wn * 64 + ((lane >> 4) & 1) * 8 + (lane & 7);
    const int   wB    = ((lane >> 3) & 1) * 4;
    const uint32_t bAddr0 = s2u(B_s) + (uint32_t)(rowB * LDW + wB) * 4u;

    float acc[2][8][4];
#pragma unroll
    for (int mt = 0; mt < 2; mt++)
#pragma unroll
        for (int nt = 0; nt < 8; nt++)
#pragma unroll
            for (int j = 0; j < 4; j++) acc[mt][nt][j] = 0.f;

    for (int kc = 0; kc < 32; kc++) {       // 32 chunks of 64 K-elements
        __syncthreads();                     // prev chunk's frag reads done
        // Load + convert f32 -> f16: 8 rows per thread per tile
#pragma unroll
        for (int i = 0; i < 8; i++) {
            const int row = row0 + 16 * i;
            float4 va = *reinterpret_cast<const float4*>(
                Abase + (size_t)(16 * i) * D2H + kc * 64);
            float4 vb = *reinterpret_cast<const float4*>(
                Bbase + (size_t)(16 * i) * D2H + kc * 64);
            const uint2 pa = make_uint2(f2h2(va.x, va.y), f2h2(va.z, va.w));
            *reinterpret_cast<uint2*>(&A_s[row * LDW + seg * 2]) = pa;
            *reinterpret_cast<uint2*>(&B_s[row * LDW + seg * 2]) =
                make_uint2(f2h2(vb.x, vb.y), f2h2(vb.z, vb.w));
            if (nc == 0)   // single writer per A tile: fp16 mirror for ctx
                *reinterpret_cast<uint2*>(
                    e16base + (size_t)(16 * i) * D2H + kc * 64) = pa;
        }
        __syncthreads();

#pragma unroll
        for (int kk = 0; kk < 4; kk++) {     // 4 k-steps of K=16
            const uint32_t koff = (uint32_t)(kk * 8 * 4);   // 8 words
            uint32_t af[2][4];
            ldsm_x4(af[0][0], af[0][1], af[0][2], af[0][3], aAddr0 + koff);
            ldsm_x4(af[1][0], af[1][1], af[1][2], af[1][3],
                    aAddr0 + 16u * LDW * 4u + koff);
            uint32_t bf[8][2];
#pragma unroll
            for (int j = 0; j < 4; j++)
                ldsm_x4(bf[2 * j][0], bf[2 * j][1],
                        bf[2 * j + 1][0], bf[2 * j + 1][1],
                        bAddr0 + (uint32_t)(j * 16 * LDW * 4) + koff);
#pragma unroll
            for (int mt = 0; mt < 2; mt++)
#pragma unroll
                for (int nt = 0; nt < 8; nt++) {
                    asm volatile(
                        "mma.sync.aligned.m16n8k16.row.col.f32.f16.f16.f32 "
                        "{%0,%1,%2,%3}, {%4,%5,%6,%7}, {%8,%9}, {%0,%1,%2,%3};"
                        : "+f"(acc[mt][nt][0]), "+f"(acc[mt][nt][1]),
                          "+f"(acc[mt][nt][2]), "+f"(acc[mt][nt][3])
                        : "r"(af[mt][0]), "r"(af[mt][1]),
                          "r"(af[mt][2]), "r"(af[mt][3]),
                          "r"(bf[nt][0]), "r"(bf[nt][1]));
                }
        }
    }

    // Epilogue: tanh(acc + wq) * V, accumulated per row
    float sp[2][2] = {{0.f, 0.f}, {0.f, 0.f}};
#pragma unroll
    for (int mt = 0; mt < 2; mt++)
#pragma unroll
        for (int nt = 0; nt < 8; nt++)
#pragma unroll
            for (int j = 0; j < 4; j++) {
                const int nl = wn * 64 + nt * 8 + 2 * tig + (j & 1);
                const float x = acc[mt][nt][j] + wq_s[nl];
                const float e = __expf(2.f * x);
                sp[mt][j >> 1] += (1.f - 2.f / (e + 1.f)) * V_s[nl];
            }

    // Reduce partial scores: 4 lanes/group share a row; 2 N-warps share a row
#pragma unroll
    for (int mt = 0; mt < 2; mt++)
#pragma unroll
        for (int rh = 0; rh < 2; rh++) {
            float v = sp[mt][rh];
            v += __shfl_xor_sync(0xffffffffu, v, 1);
            v += __shfl_xor_sync(0xffffffffu, v, 2);
            if (tig == 0)
                atomicAdd(&scores_s[wm * 32 + mt * 16 + rh * 8 + gid], v);
        }
    __syncthreads();
    if (tid < 128)   // V_b omitted: softmax is shift-invariant
        g_spart[(size_t)nc * (BB * SS) + (size_t)b * SS + stile * 128 + tid] =
            scores_s[tid];
}

// ---------------------------------------------------------------------------
// Kernel C: sum 8 N-chunk partials, softmax over S per batch
// ---------------------------------------------------------------------------
__global__ void softmax_kernel() {
    int b = blockIdx.x, tid = threadIdx.x;   // 256 threads
    __shared__ float red[256];
    float v[8];
    float mx = -1e30f;
#pragma unroll
    for (int i = 0; i < 8; i++) {
        const int idx = b * SS + i * 256 + tid;
        float x = 0.f;
#pragma unroll
        for (int p = 0; p < 8; p++) x += g_spart[p * (BB * SS) + idx];
        v[i] = x;
        mx = fmaxf(mx, x);
    }
    red[tid] = mx;
    __syncthreads();
    for (int s = 128; s > 0; s >>= 1) {
        if (tid < s) red[tid] = fmaxf(red[tid], red[tid + s]);
        __syncthreads();
    }
    mx = red[0];
    __syncthreads();
    float sum = 0.f;
#pragma unroll
    for (int i = 0; i < 8; i++) {
        v[i] = __expf(v[i] - mx);
        sum += v[i];
    }
    red[tid] = sum;
    __syncthreads();
    for (int s = 128; s > 0; s >>= 1) {
        if (tid < s) red[tid] += red[tid + s];
        __syncthreads();
    }
    const float inv = 1.f / red[0];
#pragma unroll
    for (int i = 0; i < 8; i++)
        g_weights[b * SS + i * 256 + tid] = v[i] * inv;
}

// ---------------------------------------------------------------------------
// Kernel D1: partial context over an S-chunk, reading the fp16 enc mirror
// (half the DRAM bytes of the fp32 path). Deterministic, no atomics.
// ---------------------------------------------------------------------------
__global__ void ctx_part_kernel() {
    int bb = blockIdx.x, sc = blockIdx.y, t = threadIdx.x;   // 512 threads
    __shared__ float w_s[256];
    if (t < 256) w_s[t] = g_weights[bb * SS + sc * 256 + t];
    __syncthreads();
    const __half* base =
        g_enc16 + ((size_t)bb * SS + (size_t)sc * 256) * D2H + t * 4;
    float4 acc = make_float4(0.f, 0.f, 0.f, 0.f);
#pragma unroll 4
    for (int s = 0; s < 256; s++) {
        const float w = w_s[s];
        const uint2 u = *reinterpret_cast<const uint2*>(base + (size_t)s * D2H);
        const float2 f0 = __half22float2(*reinterpret_cast<const __half2*>(&u.x));
        const float2 f1 = __half22float2(*reinterpret_cast<const __half2*>(&u.y));
        acc.x += w * f0.x; acc.y += w * f0.y;
        acc.z += w * f1.x; acc.w += w * f1.y;
    }
    *reinterpret_cast<float4*>(g_part + ((size_t)sc * BB + bb) * D2H + t * 4) = acc;
}

// Kernel D2: sum the 8 S-chunk partials -> output [B, 1, 2H]
__global__ void ctx_reduce_kernel(float* __restrict__ out) {
    int i = blockIdx.x * blockDim.x + threadIdx.x;
    float s = 0.f;
#pragma unroll
    for (int sc = 0; sc < 8; sc++) s += g_part[sc * (BB * D2H) + i];
    out[i] = s;
}

// ---------------------------------------------------------------------------
extern "C" void kernel_launch(void* const* d_in, const int* in_sizes, int n_in,
                              void* d_out, int out_size) {
    const float* enc = (const float*)d_in[0];   // [32, 2048, 2048]
    const float* dh  = (const float*)d_in[1];   // [1, 32, 1024]
    const float* W_w = (const float*)d_in[2];   // [1024, 1024]
    const float* W_b = (const float*)d_in[3];   // [1024]
    const float* U_w = (const float*)d_in[4];   // [1024, 2048]
    const float* U_b = (const float*)d_in[5];   // [1024]
    const float* V_w = (const float*)d_in[6];   // [1, 1024]
    float* out = (float*)d_out;                 // [32, 1, 2048]

    wq_kernel<<<dim3(32, 8), 128>>>(dh, W_w, W_b, U_b);
    score_kernel<<<4096, 256>>>(enc, U_w, V_w);
    softmax_kernel<<<32, 256>>>();
    ctx_part_kernel<<<dim3(32, 8), 512>>>();
    ctx_reduce_kernel<<<128, 512>>>(out);
}